// round 1
// baseline (speedup 1.0000x reference)
#include <cuda_runtime.h>

#define Sn 20000
#define En 10000
#define Kn 128
#define Dn 128
#define NEKn 40000
#define NSEn 500000
#define Bn 2048

// ---------------- static device scratch (no allocation allowed) ----------------
__device__ float g_exA[En*Dn], g_exB[En*Dn];
__device__ float g_stA[Sn*Dn], g_stB[Sn*Dn];
__device__ float g_knA[Kn*Dn], g_knB[Kn*Dn];
__device__ float g_u[Sn];
__device__ float g_w[4*Dn];
__device__ float g_agg[Sn*Dn];
__device__ float g_Bx[En*Dn], g_Cx[En*Dn];
__device__ int g_rp_ekd[Kn+1],  g_el_ekd[NEKn];
__device__ int g_rp_eks[En+1],  g_el_eks[NEKn];
__device__ int g_rp_sed[Sn+1],  g_el_sed[NSEn];
__device__ int g_rp_ses[En+1],  g_el_ses[NSEn];
__device__ int g_cnt[Sn], g_cur2[Sn];

// ---------------- CSR build ----------------
__global__ void k_zero(int* p, int n){
    int i = blockIdx.x*blockDim.x + threadIdx.x;
    if (i < n) p[i] = 0;
}

__global__ void k_hist(const int* __restrict__ keys, int nnz, int kbase, int* cnt){
    int i = blockIdx.x*blockDim.x + threadIdx.x;
    if (i < nnz) atomicAdd(&cnt[keys[i]-kbase], 1);
}

// single-block exclusive scan (n <= 20000), writes row_ptr[0..n] and cursor copy
__global__ void k_exscan(const int* __restrict__ cnt, int n, int* rp, int* cur){
    __shared__ int part[1024];
    int t = threadIdx.x;
    int per = (n + 1023) >> 10;
    int b0 = t*per;
    int b1 = b0 + per; if (b1 > n) b1 = n;
    int s = 0;
    for (int i = b0; i < b1; i++) s += cnt[i];
    part[t] = s;
    __syncthreads();
    for (int off = 1; off < 1024; off <<= 1){
        int v = (t >= off) ? part[t-off] : 0;
        __syncthreads();
        part[t] += v;
        __syncthreads();
    }
    int base = (t > 0) ? part[t-1] : 0;
    for (int i = b0; i < b1; i++){ rp[i] = base; cur[i] = base; base += cnt[i]; }
    if (t == 0) rp[n] = part[1023];
}

// stores the OPPOSITE endpoint (gather index) directly -> no double indirection later
__global__ void k_scatter(const int* __restrict__ keys, const int* __restrict__ vals,
                          int nnz, int kbase, int vbase, int* cur, int* el){
    int i = blockIdx.x*blockDim.x + threadIdx.x;
    if (i < nnz){
        int p = atomicAdd(&cur[keys[i]-kbase], 1);
        el[p] = vals[i] - vbase;
    }
}

// ---------------- per-layer small precompute: w_g = W_g @ a_g[:D] ----------------
__global__ void k_w4(const float* __restrict__ GWl, const float* __restrict__ Gal, float* wout){
    int g = blockIdx.x, t = threadIdx.x;   // 4 blocks x 128 threads
    const float* W = GWl + g*Dn*Dn;
    const float* a = Gal + g*2*Dn;
    float s = 0.f;
    #pragma unroll 8
    for (int j = 0; j < Dn; j++) s += W[t*Dn + j] * a[j];
    wout[g*Dn + t] = s;
}

// ---------------- u[r] = H[r] . w  (warp per row) ----------------
__global__ void k_u(const float* __restrict__ H, int n, const float* __restrict__ w, float* u){
    int lane = threadIdx.x & 31;
    int r = (blockIdx.x*blockDim.x + threadIdx.x) >> 5;
    if (r >= n) return;
    float4 w4 = ((const float4*)w)[lane];
    float4 h  = ((const float4*)H)[r*32 + lane];
    float p = h.x*w4.x + h.y*w4.y + h.z*w4.z + h.w*w4.w;
    #pragma unroll
    for (int o = 16; o; o >>= 1) p += __shfl_xor_sync(0xffffffffu, p, o);
    if (lane == 0) u[r] = p;
}

// ---------------- attention aggregation: out[r] = softmax_edges(u) . H rows ----------------
__global__ void k_agg(const int* __restrict__ rp, const int* __restrict__ el,
                      const float* __restrict__ u, const float* __restrict__ H,
                      float* __restrict__ out, int n){
    int lane = threadIdx.x & 31;
    int r = (blockIdx.x*blockDim.x + threadIdx.x) >> 5;
    if (r >= n) return;
    int s = rp[r], e = rp[r+1];
    float4 acc = make_float4(0.f,0.f,0.f,0.f);
    if (s == e){ ((float4*)out)[r*32 + lane] = acc; return; }
    float m = -1e30f;
    for (int i = s + lane; i < e; i += 32) m = fmaxf(m, u[el[i]]);
    #pragma unroll
    for (int o = 16; o; o >>= 1) m = fmaxf(m, __shfl_xor_sync(0xffffffffu, m, o));
    float den = 0.f;
    int i = s;
    for (; i + 1 < e; i += 2){
        int g0 = el[i], g1 = el[i+1];
        float w0 = __expf(u[g0] - m);
        float w1 = __expf(u[g1] - m);
        float4 h0 = ((const float4*)H)[g0*32 + lane];
        float4 h1 = ((const float4*)H)[g1*32 + lane];
        den += w0 + w1;
        acc.x += w0*h0.x + w1*h1.x;
        acc.y += w0*h0.y + w1*h1.y;
        acc.z += w0*h0.z + w1*h1.z;
        acc.w += w0*h0.w + w1*h1.w;
    }
    if (i < e){
        int g0 = el[i];
        float w0 = __expf(u[g0] - m);
        float4 h0 = ((const float4*)H)[g0*32 + lane];
        den += w0;
        acc.x += w0*h0.x; acc.y += w0*h0.y; acc.z += w0*h0.z; acc.w += w0*h0.w;
    }
    float inv = 1.f/den;
    acc.x *= inv; acc.y *= inv; acc.z *= inv; acc.w *= inv;
    ((float4*)out)[r*32 + lane] = acc;
}

// ---------------- Cout[rows x 128] = (Cin +) A[rows x 128] @ W[128 x 128] ----------------
// block: 256 threads, 32 rows; W + A^T in dynamic shared
__global__ void k_gemm(const float* __restrict__ A, const float* __restrict__ W,
                       const float* __restrict__ Cin, float* __restrict__ Cout, int rows){
    extern __shared__ float sm[];
    float* Ws  = sm;              // 128*128
    float* AsT = sm + Dn*Dn;      // 128*32, k-major: AsT[k*32 + r]
    int t = threadIdx.x;
    int r0 = blockIdx.x * 32;
    for (int i = t; i < Dn*Dn/4; i += 256) ((float4*)Ws)[i] = ((const float4*)W)[i];
    for (int i = t; i < 32*Dn/4; i += 256){
        int rr = i >> 5;       // local row 0..31
        int qq = i & 31;       // float4 index along k
        float4 v = (r0 + rr < rows) ? ((const float4*)A)[(size_t)(r0+rr)*32 + qq]
                                    : make_float4(0.f,0.f,0.f,0.f);
        AsT[(qq*4+0)*32 + rr] = v.x;
        AsT[(qq*4+1)*32 + rr] = v.y;
        AsT[(qq*4+2)*32 + rr] = v.z;
        AsT[(qq*4+3)*32 + rr] = v.w;
    }
    __syncthreads();
    int cq = t & 31;   // col quad 0..31
    int rq = t >> 5;   // row quad 0..7
    float acc[4][4] = {};
    #pragma unroll 8
    for (int k = 0; k < Dn; k++){
        float4 a = ((float4*)AsT)[k*8 + rq];
        float4 w = ((float4*)Ws)[k*32 + cq];
        acc[0][0] += a.x*w.x; acc[0][1] += a.x*w.y; acc[0][2] += a.x*w.z; acc[0][3] += a.x*w.w;
        acc[1][0] += a.y*w.x; acc[1][1] += a.y*w.y; acc[1][2] += a.y*w.z; acc[1][3] += a.y*w.w;
        acc[2][0] += a.z*w.x; acc[2][1] += a.z*w.y; acc[2][2] += a.z*w.z; acc[2][3] += a.z*w.w;
        acc[3][0] += a.w*w.x; acc[3][1] += a.w*w.y; acc[3][2] += a.w*w.z; acc[3][3] += a.w*w.w;
    }
    #pragma unroll
    for (int i2 = 0; i2 < 4; i2++){
        int row = r0 + rq*4 + i2;
        if (row < rows){
            float4 c = make_float4(acc[i2][0], acc[i2][1], acc[i2][2], acc[i2][3]);
            if (Cin){
                float4 ci = ((const float4*)Cin)[(size_t)row*32 + cq];
                c.x += ci.x; c.y += ci.y; c.z += ci.z; c.w += ci.w;
            }
            ((float4*)Cout)[(size_t)row*32 + cq] = c;
        }
    }
}

// ---------------- exercise combine: 2-way gated residual ----------------
__global__ void k_combine(const float* __restrict__ ex_in, const float* __restrict__ Bx,
                          const float* __restrict__ Cx, const float* __restrict__ Fwl,
                          const float* __restrict__ Fbl, float* __restrict__ ex_out){
    int lane = threadIdx.x & 31;
    int r = (blockIdx.x*blockDim.x + threadIdx.x) >> 5;
    if (r >= En) return;
    const float4* F0 = (const float4*)(Fwl);          // Fw[l][0] (256 floats)
    const float4* F1 = (const float4*)(Fwl + 2*Dn);   // Fw[l][1]
    float4 e4 = ((const float4*)ex_in)[r*32 + lane];
    float4 b4 = ((const float4*)Bx)[r*32 + lane];
    float4 c4 = ((const float4*)Cx)[r*32 + lane];
    float4 f0a = F0[lane], f0b = F0[lane+32];
    float4 f1a = F1[lane], f1b = F1[lane+32];
    float s1 = e4.x*f0a.x + e4.y*f0a.y + e4.z*f0a.z + e4.w*f0a.w
             + b4.x*f0b.x + b4.y*f0b.y + b4.z*f0b.z + b4.w*f0b.w;
    float s2 = e4.x*f1a.x + e4.y*f1a.y + e4.z*f1a.z + e4.w*f1a.w
             + c4.x*f1b.x + c4.y*f1b.y + c4.z*f1b.z + c4.w*f1b.w;
    #pragma unroll
    for (int o = 16; o; o >>= 1){
        s1 += __shfl_xor_sync(0xffffffffu, s1, o);
        s2 += __shfl_xor_sync(0xffffffffu, s2, o);
    }
    s1 += Fbl[0]; s2 += Fbl[1];
    float mm = fmaxf(s1, s2);
    float p0 = __expf(s1 - mm), p1 = __expf(s2 - mm);
    float inv = 1.f/(p0 + p1);
    p0 *= inv; p1 *= inv;
    float4 o4;
    o4.x = e4.x + p0*b4.x + p1*c4.x;
    o4.y = e4.y + p0*b4.y + p1*c4.y;
    o4.z = e4.z + p0*b4.z + p1*c4.z;
    o4.w = e4.w + p0*b4.w + p1*c4.w;
    ((float4*)ex_out)[r*32 + lane] = o4;
}

// ---------------- final broadcast materialization ----------------
__global__ void k_writeout(const float* __restrict__ st_f, const float* __restrict__ ex_f,
                           const float* __restrict__ kn_f, const float* __restrict__ disc,
                           const int* __restrict__ sid, const int* __restrict__ eid,
                           float* __restrict__ out){
    int b = blockIdx.x;
    int t = threadIdx.x;  // 256
    __shared__ float4 srow[32], erow[32];
    int si = sid[b], ei = eid[b];
    if (t < 32)      srow[t]    = ((const float4*)st_f)[(size_t)si*32 + t];
    else if (t < 64) erow[t-32] = ((const float4*)ex_f)[(size_t)ei*32 + (t-32)];
    __syncthreads();
    const size_t TS = (size_t)Bn*Dn*Dn;  // 33,554,432 floats per tensor
    float4* o1 = (float4*)out + (size_t)b*4096;
    float4* o2 = (float4*)(out + TS) + (size_t)b*4096;
    float4* o3 = (float4*)(out + 2*TS + Bn) + (size_t)b*4096;
    const float4* kn4 = (const float4*)kn_f;
    float4 sv = srow[t & 31], ev = erow[t & 31];
    #pragma unroll
    for (int k = 0; k < 16; k++){
        int idx = t + 256*k;
        o1[idx] = sv;
        o2[idx] = ev;
        o3[idx] = kn4[idx];
    }
    if (t == 0) out[2*TS + (size_t)b] = disc[ei];
}

// ---------------- host orchestration ----------------
extern "C" void kernel_launch(void* const* d_in, const int* in_sizes, int n_in,
                              void* d_out, int out_size){
    (void)in_sizes; (void)n_in; (void)out_size;
    const float* stu  = (const float*)d_in[0];
    const float* exer = (const float*)d_in[1];
    const float* kn   = (const float*)d_in[2];
    const float* disc = (const float*)d_in[3];
    const float* GW   = (const float*)d_in[4];
    const float* Ga   = (const float*)d_in[5];
    const float* Fw   = (const float*)d_in[6];
    const float* Fb   = (const float*)d_in[7];
    const int* sid = (const int*)d_in[9];
    const int* eid = (const int*)d_in[10];
    const int* eks = (const int*)d_in[11];
    const int* ekd = (const int*)d_in[12];
    const int* ses = (const int*)d_in[13];
    const int* sed = (const int*)d_in[14];
    float* out = (float*)d_out;

    void *pexA,*pexB,*pstA,*pstB,*pknA,*pknB,*pu,*pw,*pagg,*pBx,*pCx;
    void *prp1,*pel1,*prp2,*pel2,*prp3,*pel3,*prp4,*pel4,*pcnt,*pcur;
    cudaGetSymbolAddress(&pexA, g_exA); cudaGetSymbolAddress(&pexB, g_exB);
    cudaGetSymbolAddress(&pstA, g_stA); cudaGetSymbolAddress(&pstB, g_stB);
    cudaGetSymbolAddress(&pknA, g_knA); cudaGetSymbolAddress(&pknB, g_knB);
    cudaGetSymbolAddress(&pu, g_u);     cudaGetSymbolAddress(&pw, g_w);
    cudaGetSymbolAddress(&pagg, g_agg);
    cudaGetSymbolAddress(&pBx, g_Bx);   cudaGetSymbolAddress(&pCx, g_Cx);
    cudaGetSymbolAddress(&prp1, g_rp_ekd); cudaGetSymbolAddress(&pel1, g_el_ekd);
    cudaGetSymbolAddress(&prp2, g_rp_eks); cudaGetSymbolAddress(&pel2, g_el_eks);
    cudaGetSymbolAddress(&prp3, g_rp_sed); cudaGetSymbolAddress(&pel3, g_el_sed);
    cudaGetSymbolAddress(&prp4, g_rp_ses); cudaGetSymbolAddress(&pel4, g_el_ses);
    cudaGetSymbolAddress(&pcnt, g_cnt);    cudaGetSymbolAddress(&pcur, g_cur2);

    cudaFuncSetAttribute(k_gemm, cudaFuncAttributeMaxDynamicSharedMemorySize, 81920);

    int* cnt = (int*)pcnt; int* cur = (int*)pcur;
    float* uv = (float*)pu; float* wv = (float*)pw; float* agg = (float*)pagg;
    float* Bx = (float*)pBx; float* Cx = (float*)pCx;

    auto build = [&](const int* keys, const int* vals, int nnz, int kbase, int vbase,
                     int n, int* rp, int* el){
        k_zero<<<(n+255)/256, 256>>>(cnt, n);
        k_hist<<<(nnz+255)/256, 256>>>(keys, nnz, kbase, cnt);
        k_exscan<<<1, 1024>>>(cnt, n, rp, cur);
        k_scatter<<<(nnz+255)/256, 256>>>(keys, vals, nnz, kbase, vbase, cur, el);
    };
    // four orientations (edges constant across both fusion layers)
    build(ekd, eks, NEKn, En, 0, Kn, (int*)prp1, (int*)pel1);  // kn <- ex
    build(eks, ekd, NEKn, 0, En, En, (int*)prp2, (int*)pel2);  // ex <- kn
    build(sed, ses, NSEn, En, 0, Sn, (int*)prp3, (int*)pel3);  // st <- ex
    build(ses, sed, NSEn, 0, En, En, (int*)prp4, (int*)pel4);  // ex <- st

    const float* exc = exer; const float* stc = stu; const float* knc = kn;
    float* exn = (float*)pexA; float* stn = (float*)pstA; float* knn = (float*)pknA;

    for (int l = 0; l < 2; l++){
        const float* GWl = GW + l*4*Dn*Dn;
        const float* Gal = Ga + l*4*2*Dn;
        const float* Fwl = Fw + l*3*2*Dn;
        const float* Fbl = Fb + l*3;
        k_w4<<<4, 128>>>(GWl, Gal, wv);

        // kfe: aggregate ex rows into kn nodes, apply W0, residual onto kn
        k_u<<<(En*32+255)/256, 256>>>(exc, En, wv + 0*Dn, uv);
        k_agg<<<(Kn*32+255)/256, 256>>>((int*)prp1, (int*)pel1, uv, exc, agg, Kn);
        k_gemm<<<(Kn+31)/32, 256, 81920>>>(agg, GWl + 0*Dn*Dn, knc, knn, Kn);

        // efk: aggregate kn rows into ex nodes, apply W1 -> Bx
        k_u<<<(Kn*32+255)/256, 256>>>(knc, Kn, wv + 1*Dn, uv);
        k_agg<<<(En*32+255)/256, 256>>>((int*)prp2, (int*)pel2, uv, knc, agg, En);
        k_gemm<<<(En+31)/32, 256, 81920>>>(agg, GWl + 1*Dn*Dn, nullptr, Bx, En);

        // ufe: aggregate ex rows into st nodes, apply W2, residual onto st
        k_u<<<(En*32+255)/256, 256>>>(exc, En, wv + 2*Dn, uv);
        k_agg<<<(Sn*32+255)/256, 256>>>((int*)prp3, (int*)pel3, uv, exc, agg, Sn);
        k_gemm<<<(Sn+31)/32, 256, 81920>>>(agg, GWl + 2*Dn*Dn, stc, stn, Sn);

        // efu: aggregate st rows into ex nodes, apply W3 -> Cx
        k_u<<<(Sn*32+255)/256, 256>>>(stc, Sn, wv + 3*Dn, uv);
        k_agg<<<(En*32+255)/256, 256>>>((int*)prp4, (int*)pel4, uv, stc, agg, En);
        k_gemm<<<(En+31)/32, 256, 81920>>>(agg, GWl + 3*Dn*Dn, nullptr, Cx, En);

        // gated exercise residual
        k_combine<<<(En*32+255)/256, 256>>>(exc, Bx, Cx, Fwl, Fbl, exn);

        exc = exn; stc = stn; knc = knn;
        exn = (float*)pexB; stn = (float*)pstB; knn = (float*)pknB;
    }

    k_writeout<<<Bn, 256>>>(stc, exc, knc, disc, sid, eid, out);
}

// round 2
// speedup vs baseline: 1.4504x; 1.4504x over previous
#include <cuda_runtime.h>

#define Sn 20000
#define En 10000
#define Kn 128
#define Dn 128
#define NEKn 40000
#define NSEn 500000
#define Bn 2048

// cnt/cur layout offsets
#define O_EKD 0
#define O_EKS (Kn)
#define O_SED (Kn+En)
#define O_SES (Kn+En+Sn)
#define NCNT  (Kn+2*En+Sn)

// u layout offsets
#define U3 0
#define U0 (Sn)
#define U2 (Sn+En)
#define U1 (Sn+2*En)
#define NU (Sn+2*En+Kn)

// agg row layout (rows of 128 floats)
#define AGG_S 0
#define AGG_C (Sn)
#define AGG_B (Sn+En)
#define AGG_K (Sn+2*En)
#define NAGG  (Sn+2*En+Kn)

// ---------------- static device scratch ----------------
__device__ float g_exA[En*Dn], g_exB[En*Dn];
__device__ float g_stA[Sn*Dn], g_stB[Sn*Dn];
__device__ float g_knA[Kn*Dn], g_knB[Kn*Dn];
__device__ float g_uAll[NU];
__device__ float g_w[8*Dn];
__device__ float g_aggAll[(size_t)NAGG*Dn];
__device__ float g_Bx[En*Dn], g_Cx[En*Dn];
__device__ int g_rp_ekd[Kn+1],  g_el_ekd[NEKn];
__device__ int g_rp_eks[En+1],  g_el_eks[NEKn];
__device__ int g_rp_sed[Sn+1],  g_el_sed[NSEn];
__device__ int g_rp_ses[En+1],  g_el_ses[NSEn];
__device__ int g_cntAll[NCNT], g_curAll[NCNT];

// ---------------- fused CSR build ----------------
__global__ void k_hist(const int* __restrict__ eks, const int* __restrict__ ekd,
                       const int* __restrict__ ses, const int* __restrict__ sed,
                       int* __restrict__ cnt){
    int i = blockIdx.x*blockDim.x + threadIdx.x;
    if (i < NEKn){
        atomicAdd(&cnt[O_EKD + ekd[i]-En], 1);
        atomicAdd(&cnt[O_EKS + eks[i]], 1);
    }
    if (i < NSEn){
        atomicAdd(&cnt[O_SED + sed[i]-En], 1);
        atomicAdd(&cnt[O_SES + ses[i]], 1);
    }
}

// 4 blocks, one per CSR array: exclusive scan -> rp + cursor
__global__ void k_scan4(const int* __restrict__ cntAll, int* __restrict__ curAll,
                        int* rp0, int* rp1, int* rp2, int* rp3){
    __shared__ int part[1024];
    int b = blockIdx.x, t = threadIdx.x;
    int off, n; int* rp;
    if      (b == 0){ off = O_EKD; n = Kn; rp = rp0; }
    else if (b == 1){ off = O_EKS; n = En; rp = rp1; }
    else if (b == 2){ off = O_SED; n = Sn; rp = rp2; }
    else            { off = O_SES; n = En; rp = rp3; }
    const int* cnt = cntAll + off;
    int* cur = curAll + off;
    int per = (n + 1023) >> 10;
    int b0 = t*per, b1 = b0 + per; if (b1 > n) b1 = n;
    int s = 0;
    for (int i = b0; i < b1; i++) s += cnt[i];
    part[t] = s;
    __syncthreads();
    for (int o = 1; o < 1024; o <<= 1){
        int v = (t >= o) ? part[t-o] : 0;
        __syncthreads();
        part[t] += v;
        __syncthreads();
    }
    int base = (t > 0) ? part[t-1] : 0;
    for (int i = b0; i < b1; i++){ rp[i] = base; cur[i] = base; base += cnt[i]; }
    if (t == 0) rp[n] = part[1023];
}

__global__ void k_scatter(const int* __restrict__ eks, const int* __restrict__ ekd,
                          const int* __restrict__ ses, const int* __restrict__ sed,
                          int* __restrict__ cur,
                          int* el_ekd, int* el_eks, int* el_sed, int* el_ses){
    int i = blockIdx.x*blockDim.x + threadIdx.x;
    if (i < NEKn){
        int s = eks[i], d = ekd[i]-En;
        int p0 = atomicAdd(&cur[O_EKD + d], 1); el_ekd[p0] = s;
        int p1 = atomicAdd(&cur[O_EKS + s], 1); el_eks[p1] = d;
    }
    if (i < NSEn){
        int s = ses[i], d = sed[i]-En;
        int p2 = atomicAdd(&cur[O_SED + d], 1); el_sed[p2] = s;
        int p3 = atomicAdd(&cur[O_SES + s], 1); el_ses[p3] = d;
    }
}

// ---------------- w_g = W_g @ a_g[:D] for all 8 (layer,group) ----------------
__global__ void k_w8(const float* __restrict__ GW, const float* __restrict__ Ga, float* wout){
    int g = blockIdx.x, t = threadIdx.x;   // 8 blocks x 128 threads
    const float* W = GW + (size_t)g*Dn*Dn;
    const float* a = Ga + (size_t)g*2*Dn;
    float s = 0.f;
    #pragma unroll 8
    for (int j = 0; j < Dn; j++) s += W[t*Dn + j] * a[j];
    wout[g*Dn + t] = s;
}

// ---------------- fused u: one read of each node matrix ----------------
__global__ void k_u(const float* __restrict__ st, const float* __restrict__ ex,
                    const float* __restrict__ kn, const float* __restrict__ wv,
                    float* __restrict__ uAll){
    int lane = threadIdx.x & 31;
    int r = (blockIdx.x*blockDim.x + threadIdx.x) >> 5;
    if (r < Sn){
        float4 w3 = ((const float4*)(wv + 3*Dn))[lane];
        float4 h = ((const float4*)st)[(size_t)r*32 + lane];
        float p = h.x*w3.x + h.y*w3.y + h.z*w3.z + h.w*w3.w;
        #pragma unroll
        for (int o = 16; o; o >>= 1) p += __shfl_xor_sync(0xffffffffu, p, o);
        if (lane == 0) uAll[U3 + r] = p;
        return;
    }
    r -= Sn;
    if (r < En){
        float4 w0 = ((const float4*)(wv + 0*Dn))[lane];
        float4 w2 = ((const float4*)(wv + 2*Dn))[lane];
        float4 h = ((const float4*)ex)[(size_t)r*32 + lane];
        float p0 = h.x*w0.x + h.y*w0.y + h.z*w0.z + h.w*w0.w;
        float p2 = h.x*w2.x + h.y*w2.y + h.z*w2.z + h.w*w2.w;
        #pragma unroll
        for (int o = 16; o; o >>= 1){
            p0 += __shfl_xor_sync(0xffffffffu, p0, o);
            p2 += __shfl_xor_sync(0xffffffffu, p2, o);
        }
        if (lane == 0){ uAll[U0 + r] = p0; uAll[U2 + r] = p2; }
        return;
    }
    r -= En;
    if (r < Kn){
        float4 w1 = ((const float4*)(wv + 1*Dn))[lane];
        float4 h = ((const float4*)kn)[(size_t)r*32 + lane];
        float p = h.x*w1.x + h.y*w1.y + h.z*w1.z + h.w*w1.w;
        #pragma unroll
        for (int o = 16; o; o >>= 1) p += __shfl_xor_sync(0xffffffffu, p, o);
        if (lane == 0) uAll[U1 + r] = p;
    }
}

// ---------------- fused attention aggregation (warp per dst row) ----------------
__device__ __forceinline__ void agg_row(const int* __restrict__ rp, const int* __restrict__ el,
                                        const float* __restrict__ u, const float* __restrict__ H,
                                        float* __restrict__ out, int r, int lane){
    int s = rp[r], e = rp[r+1];
    float4 acc = make_float4(0.f,0.f,0.f,0.f);
    if (s == e){ ((float4*)out)[(size_t)r*32 + lane] = acc; return; }
    float m = -1e30f;
    for (int i = s + lane; i < e; i += 32) m = fmaxf(m, u[el[i]]);
    #pragma unroll
    for (int o = 16; o; o >>= 1) m = fmaxf(m, __shfl_xor_sync(0xffffffffu, m, o));
    float den = 0.f;
    int i = s;
    for (; i + 1 < e; i += 2){
        int g0 = el[i], g1 = el[i+1];
        float w0 = __expf(u[g0] - m);
        float w1 = __expf(u[g1] - m);
        float4 h0 = ((const float4*)H)[(size_t)g0*32 + lane];
        float4 h1 = ((const float4*)H)[(size_t)g1*32 + lane];
        den += w0 + w1;
        acc.x += w0*h0.x + w1*h1.x;
        acc.y += w0*h0.y + w1*h1.y;
        acc.z += w0*h0.z + w1*h1.z;
        acc.w += w0*h0.w + w1*h1.w;
    }
    if (i < e){
        int g0 = el[i];
        float w0 = __expf(u[g0] - m);
        float4 h0 = ((const float4*)H)[(size_t)g0*32 + lane];
        den += w0;
        acc.x += w0*h0.x; acc.y += w0*h0.y; acc.z += w0*h0.z; acc.w += w0*h0.w;
    }
    float inv = 1.f/den;
    acc.x *= inv; acc.y *= inv; acc.z *= inv; acc.w *= inv;
    ((float4*)out)[(size_t)r*32 + lane] = acc;
}

__global__ void k_agg(const float* __restrict__ st, const float* __restrict__ ex,
                      const float* __restrict__ kn, const float* __restrict__ uAll,
                      float* __restrict__ aggAll){
    int lane = threadIdx.x & 31;
    int r = (blockIdx.x*blockDim.x + threadIdx.x) >> 5;
    if (r < Sn){                       // ufe: st <- ex, weights u2
        agg_row(g_rp_sed, g_el_sed, uAll + U2, ex, g_aggAll + (size_t)AGG_S*Dn, r, lane);
        return;
    }
    r -= Sn;
    if (r < En){                       // efu: ex <- st, weights u3
        agg_row(g_rp_ses, g_el_ses, uAll + U3, st, g_aggAll + (size_t)AGG_C*Dn, r, lane);
        return;
    }
    r -= En;
    if (r < En){                       // efk: ex <- kn, weights u1
        agg_row(g_rp_eks, g_el_eks, uAll + U1, kn, g_aggAll + (size_t)AGG_B*Dn, r, lane);
        return;
    }
    r -= En;
    if (r < Kn){                       // kfe: kn <- ex, weights u0
        agg_row(g_rp_ekd, g_el_ekd, uAll + U0, ex, g_aggAll + (size_t)AGG_K*Dn, r, lane);
    }
    (void)aggAll;
}

// ---------------- fused GEMM: 64-row tiles, 4 segments, one launch ----------------
struct GemmSeg { const float* A; const float* W; const float* Cin; float* Cout; int rows; };
struct GemmArgs { GemmSeg s[4]; int nb[4]; };   // nb = blocks per segment

#define AST_STRIDE 68   // padded (2-way STS conflict, float4-aligned)

__global__ void k_gemm(GemmArgs ga){
    extern __shared__ float sm[];
    float* Ws  = sm;                     // 128*128
    float* AsT = sm + Dn*Dn;             // [k][r] stride 68
    int blk = blockIdx.x;
    int si = 0;
    while (si < 3 && blk >= ga.nb[si]){ blk -= ga.nb[si]; si++; }
    const GemmSeg sg = ga.s[si];
    int t = threadIdx.x;
    int r0 = blk * 64;
    // load W (64KB) coalesced
    for (int i = t; i < Dn*Dn/4; i += 256) ((float4*)Ws)[i] = ((const float4*)sg.W)[i];
    // load A tile transposed
    for (int idx = t; idx < 64*32; idx += 256){
        int rr = idx >> 5;            // local row 0..63
        int qq = idx & 31;            // float4 index along k
        float4 v = (r0 + rr < sg.rows) ? ((const float4*)sg.A)[(size_t)(r0+rr)*32 + qq]
                                       : make_float4(0.f,0.f,0.f,0.f);
        AsT[(qq*4+0)*AST_STRIDE + rr] = v.x;
        AsT[(qq*4+1)*AST_STRIDE + rr] = v.y;
        AsT[(qq*4+2)*AST_STRIDE + rr] = v.z;
        AsT[(qq*4+3)*AST_STRIDE + rr] = v.w;
    }
    __syncthreads();
    int cq = t & 31;   // col quad
    int rq = t >> 5;   // row octet 0..7
    const float4* Ws4  = (const float4*)Ws;
    const float4* AsT4 = (const float4*)AsT;
    float acc[8][4] = {};
    #pragma unroll 4
    for (int k = 0; k < Dn; k++){
        float4 w = Ws4[k*32 + cq];
        float4 a01 = AsT4[k*(AST_STRIDE/4) + rq*2];
        float4 a23 = AsT4[k*(AST_STRIDE/4) + rq*2 + 1];
        float av[8] = {a01.x,a01.y,a01.z,a01.w,a23.x,a23.y,a23.z,a23.w};
        #pragma unroll
        for (int j = 0; j < 8; j++){
            acc[j][0] += av[j]*w.x;
            acc[j][1] += av[j]*w.y;
            acc[j][2] += av[j]*w.z;
            acc[j][3] += av[j]*w.w;
        }
    }
    #pragma unroll
    for (int j = 0; j < 8; j++){
        int row = r0 + rq*8 + j;
        if (row < sg.rows){
            float4 c = make_float4(acc[j][0], acc[j][1], acc[j][2], acc[j][3]);
            if (sg.Cin){
                float4 ci = ((const float4*)sg.Cin)[(size_t)row*32 + cq];
                c.x += ci.x; c.y += ci.y; c.z += ci.z; c.w += ci.w;
            }
            ((float4*)sg.Cout)[(size_t)row*32 + cq] = c;
        }
    }
}

// ---------------- exercise combine: 2-way gated residual ----------------
__global__ void k_combine(const float* __restrict__ ex_in, const float* __restrict__ Bx,
                          const float* __restrict__ Cx, const float* __restrict__ Fwl,
                          const float* __restrict__ Fbl, float* __restrict__ ex_out){
    int lane = threadIdx.x & 31;
    int r = (blockIdx.x*blockDim.x + threadIdx.x) >> 5;
    if (r >= En) return;
    const float4* F0 = (const float4*)(Fwl);
    const float4* F1 = (const float4*)(Fwl + 2*Dn);
    float4 e4 = ((const float4*)ex_in)[(size_t)r*32 + lane];
    float4 b4 = ((const float4*)Bx)[(size_t)r*32 + lane];
    float4 c4 = ((const float4*)Cx)[(size_t)r*32 + lane];
    float4 f0a = F0[lane], f0b = F0[lane+32];
    float4 f1a = F1[lane], f1b = F1[lane+32];
    float s1 = e4.x*f0a.x + e4.y*f0a.y + e4.z*f0a.z + e4.w*f0a.w
             + b4.x*f0b.x + b4.y*f0b.y + b4.z*f0b.z + b4.w*f0b.w;
    float s2 = e4.x*f1a.x + e4.y*f1a.y + e4.z*f1a.z + e4.w*f1a.w
             + c4.x*f1b.x + c4.y*f1b.y + c4.z*f1b.z + c4.w*f1b.w;
    #pragma unroll
    for (int o = 16; o; o >>= 1){
        s1 += __shfl_xor_sync(0xffffffffu, s1, o);
        s2 += __shfl_xor_sync(0xffffffffu, s2, o);
    }
    s1 += Fbl[0]; s2 += Fbl[1];
    float mm = fmaxf(s1, s2);
    float p0 = __expf(s1 - mm), p1 = __expf(s2 - mm);
    float inv = 1.f/(p0 + p1);
    p0 *= inv; p1 *= inv;
    float4 o4;
    o4.x = e4.x + p0*b4.x + p1*c4.x;
    o4.y = e4.y + p0*b4.y + p1*c4.y;
    o4.z = e4.z + p0*b4.z + p1*c4.z;
    o4.w = e4.w + p0*b4.w + p1*c4.w;
    ((float4*)ex_out)[(size_t)r*32 + lane] = o4;
}

// ---------------- final broadcast materialization ----------------
__global__ void k_writeout(const float* __restrict__ st_f, const float* __restrict__ ex_f,
                           const float* __restrict__ kn_f, const float* __restrict__ disc,
                           const int* __restrict__ sid, const int* __restrict__ eid,
                           float* __restrict__ out){
    int b = blockIdx.x;
    int t = threadIdx.x;  // 256
    __shared__ float4 srow[32], erow[32];
    int si = sid[b], ei = eid[b];
    if (t < 32)      srow[t]    = ((const float4*)st_f)[(size_t)si*32 + t];
    else if (t < 64) erow[t-32] = ((const float4*)ex_f)[(size_t)ei*32 + (t-32)];
    __syncthreads();
    const size_t TS = (size_t)Bn*Dn*Dn;
    float4* o1 = (float4*)out + (size_t)b*4096;
    float4* o2 = (float4*)(out + TS) + (size_t)b*4096;
    float4* o3 = (float4*)(out + 2*TS + Bn) + (size_t)b*4096;
    const float4* kn4 = (const float4*)kn_f;
    float4 sv = srow[t & 31], ev = erow[t & 31];
    #pragma unroll
    for (int k = 0; k < 16; k++){
        int idx = t + 256*k;
        o1[idx] = sv;
        o2[idx] = ev;
        o3[idx] = kn4[idx];
    }
    if (t == 0) out[2*TS + (size_t)b] = disc[ei];
}

// ---------------- host orchestration ----------------
extern "C" void kernel_launch(void* const* d_in, const int* in_sizes, int n_in,
                              void* d_out, int out_size){
    (void)in_sizes; (void)n_in; (void)out_size;
    const float* stu  = (const float*)d_in[0];
    const float* exer = (const float*)d_in[1];
    const float* kn   = (const float*)d_in[2];
    const float* disc = (const float*)d_in[3];
    const float* GW   = (const float*)d_in[4];
    const float* Ga   = (const float*)d_in[5];
    const float* Fw   = (const float*)d_in[6];
    const float* Fb   = (const float*)d_in[7];
    const int* sid = (const int*)d_in[9];
    const int* eid = (const int*)d_in[10];
    const int* eks = (const int*)d_in[11];
    const int* ekd = (const int*)d_in[12];
    const int* ses = (const int*)d_in[13];
    const int* sed = (const int*)d_in[14];
    float* out = (float*)d_out;

    void *pexA,*pexB,*pstA,*pstB,*pknA,*pknB,*pu,*pw,*pagg,*pBx,*pCx;
    void *prp1,*pel1,*prp2,*pel2,*prp3,*pel3,*prp4,*pel4,*pcnt,*pcur;
    cudaGetSymbolAddress(&pexA, g_exA); cudaGetSymbolAddress(&pexB, g_exB);
    cudaGetSymbolAddress(&pstA, g_stA); cudaGetSymbolAddress(&pstB, g_stB);
    cudaGetSymbolAddress(&pknA, g_knA); cudaGetSymbolAddress(&pknB, g_knB);
    cudaGetSymbolAddress(&pu, g_uAll);  cudaGetSymbolAddress(&pw, g_w);
    cudaGetSymbolAddress(&pagg, g_aggAll);
    cudaGetSymbolAddress(&pBx, g_Bx);   cudaGetSymbolAddress(&pCx, g_Cx);
    cudaGetSymbolAddress(&prp1, g_rp_ekd); cudaGetSymbolAddress(&pel1, g_el_ekd);
    cudaGetSymbolAddress(&prp2, g_rp_eks); cudaGetSymbolAddress(&pel2, g_el_eks);
    cudaGetSymbolAddress(&prp3, g_rp_sed); cudaGetSymbolAddress(&pel3, g_el_sed);
    cudaGetSymbolAddress(&prp4, g_rp_ses); cudaGetSymbolAddress(&pel4, g_el_ses);
    cudaGetSymbolAddress(&pcnt, g_cntAll); cudaGetSymbolAddress(&pcur, g_curAll);

    static int smem_set = 0;
    if (!smem_set){
        cudaFuncSetAttribute(k_gemm, cudaFuncAttributeMaxDynamicSharedMemorySize,
                             (Dn*Dn + Dn*AST_STRIDE)*4);
        smem_set = 1;
    }

    float* uv = (float*)pu; float* wv = (float*)pw; float* agg = (float*)pagg;
    float* Bx = (float*)pBx; float* Cx = (float*)pCx;

    // all 8 attention projection vectors in one tiny launch
    k_w8<<<8, 128>>>(GW, Ga, wv);

    // fused CSR build: memset + hist + scan + scatter  (4 graph nodes)
    cudaMemsetAsync(pcnt, 0, NCNT*sizeof(int));
    int eg = (NSEn + 255)/256;
    k_hist<<<eg, 256>>>(eks, ekd, ses, sed, (int*)pcnt);
    k_scan4<<<4, 1024>>>((int*)pcnt, (int*)pcur, (int*)prp1, (int*)prp2, (int*)prp3, (int*)prp4);
    k_scatter<<<eg, 256>>>(eks, ekd, ses, sed, (int*)pcur,
                           (int*)pel1, (int*)pel2, (int*)pel3, (int*)pel4);

    const float* exc = exer; const float* stc = stu; const float* knc = kn;
    float* exn = (float*)pexA; float* stn = (float*)pstA; float* knn = (float*)pknA;

    const int NWU = Sn + En + Kn;
    const int NWA = NAGG;

    for (int l = 0; l < 2; l++){
        const float* wvL = wv + l*4*Dn;
        const float* GWl = GW + (size_t)l*4*Dn*Dn;
        const float* Fwl = Fw + l*3*2*Dn;
        const float* Fbl = Fb + l*3;

        k_u<<<(NWU*32 + 255)/256, 256>>>(stc, exc, knc, wvL, uv);
        k_agg<<<(NWA*32 + 255)/256, 256>>>(stc, exc, knc, uv, agg);

        GemmArgs ga;
        ga.s[0] = { agg + (size_t)AGG_S*Dn, GWl + 2*Dn*Dn, stc,    stn, Sn };
        ga.s[1] = { agg + (size_t)AGG_C*Dn, GWl + 3*Dn*Dn, nullptr, Cx, En };
        ga.s[2] = { agg + (size_t)AGG_B*Dn, GWl + 1*Dn*Dn, nullptr, Bx, En };
        ga.s[3] = { agg + (size_t)AGG_K*Dn, GWl + 0*Dn*Dn, knc,    knn, Kn };
        ga.nb[0] = (Sn + 63)/64; ga.nb[1] = (En + 63)/64;
        ga.nb[2] = (En + 63)/64; ga.nb[3] = (Kn + 63)/64;
        int nbt = ga.nb[0] + ga.nb[1] + ga.nb[2] + ga.nb[3];
        k_gemm<<<nbt, 256, (Dn*Dn + Dn*AST_STRIDE)*4>>>(ga);

        k_combine<<<(En*32 + 255)/256, 256>>>(exc, Bx, Cx, Fwl, Fbl, exn);

        exc = exn; stc = stn; knc = knn;
        exn = (float*)pexB; stn = (float*)pstB; knn = (float*)pknB;
    }

    k_writeout<<<Bn, 256>>>(stc, exc, knc, disc, sid, eid, out);
}